// round 8
// baseline (speedup 1.0000x reference)
#include <cuda_runtime.h>
#include <math.h>
#include <stdint.h>

#define SEQ   512
#define HID   512
#define IN0   1088
#define IN1   1024
#define GATES 2048
#define MLPH  100
#define PAIRD 2048
#define RCTAS 64   // CTAs per LSTM direction
#define WIN   1.5f

// ---------------- device scratch (no allocations allowed) ----------------
__device__ float g_x0[SEQ * IN0];
__device__ float g_xw0[SEQ * GATES];
__device__ float g_xw1[SEQ * GATES];
__device__ float g_h0[SEQ * 2 * HID];
__device__ float g_h1[SEQ * 2 * HID];
__device__ float g_sh[SEQ * MLPH];
__device__ float g_sm[SEQ * MLPH];
__device__ float g_scores[SEQ * SEQ];
// self-validating h exchange: [dir][buffer=t&1][granule 0..255] (8B = 2 h values)
__device__ __align__(128) unsigned long long g_hx[2][2][256];
__device__ __align__(128) unsigned g_cnt[2][32];    // one-time start barrier
__device__ __align__(128) unsigned g_exit[2][32];   // exit/reset barrier

// ---------------- helpers ----------------
__device__ __forceinline__ unsigned ld_acq(const unsigned* p) {
    unsigned v;
    asm volatile("ld.acquire.gpu.u32 %0, [%1];" : "=r"(v) : "l"(p) : "memory");
    return v;
}
__device__ __forceinline__ unsigned long long ld_rlx64(const unsigned long long* p) {
    unsigned long long v;
    asm volatile("ld.relaxed.gpu.global.b64 %0, [%1];" : "=l"(v) : "l"(p) : "memory");
    return v;
}
__device__ __forceinline__ void st_rlx64(unsigned long long* p, unsigned long long v) {
    asm volatile("st.relaxed.gpu.global.b64 [%0], %1;" :: "l"(p), "l"(v) : "memory");
}
__device__ __forceinline__ float tanhap(float x) {             // HW tanh
    float y;
    asm("tanh.approx.f32 %0, %1;" : "=f"(y) : "f"(x));
    return y;
}
__device__ __forceinline__ float sigap(float x) {              // sigmoid via HW tanh
    return fmaf(0.5f, tanhap(0.5f * x), 0.5f);
}

// ---------------- embeddings ----------------
__global__ void embed_kernel(const int* __restrict__ wi, const int* __restrict__ pi,
                             const float* __restrict__ we, const float* __restrict__ pe) {
    int t = blockIdx.x;
    int w = wi[t], p = pi[t];
    const float* wr = we + (size_t)w * 1024;
    const float* pr = pe + (size_t)p * 64;
    float* out = g_x0 + (size_t)t * IN0;
    for (int i = threadIdx.x; i < 1024; i += blockDim.x) out[i] = wr[i];
    for (int i = threadIdx.x; i < 64; i += blockDim.x) out[1024 + i] = pr[i];
}

// ---- dual GEMM: z selects (B, bias, C); C[M,N] = A[M,K] * B[N,K]^T (+bias) ----
// BM=64, BN=64, BK=16, 256 threads, 4x4 register tile, register double-buffered.
__global__ void gemm_dual(const float* __restrict__ A, int lda,
                          const float* __restrict__ B0, const float* __restrict__ B1, int ldb,
                          const float* __restrict__ bias0, const float* __restrict__ bias1,
                          float* __restrict__ C0, float* __restrict__ C1, int ldc,
                          int M, int N, int K) {
    const float* B = blockIdx.z ? B1 : B0;
    const float* bias = blockIdx.z ? bias1 : bias0;
    float* C = blockIdx.z ? C1 : C0;

    __shared__ __align__(16) float As[16][68];
    __shared__ __align__(16) float Bs[16][68];
    int bm = blockIdx.y * 64, bn = blockIdx.x * 64;
    int tid = threadIdx.x;
    int tx = tid & 15, ty = tid >> 4;
    int lr = tid >> 2;
    int lk = (tid & 3) * 4;

    float acc[4][4];
#pragma unroll
    for (int i = 0; i < 4; i++)
#pragma unroll
        for (int j = 0; j < 4; j++) acc[i][j] = 0.f;

    int rowa = bm + lr;
    int rowb = bn + lr;

    // preload tile 0
    float4 va = make_float4(0.f, 0.f, 0.f, 0.f);
    float4 vb = make_float4(0.f, 0.f, 0.f, 0.f);
    if (rowa < M) va = *(const float4*)(A + (size_t)rowa * lda + lk);
    if (rowb < N) vb = *(const float4*)(B + (size_t)rowb * ldb + lk);

    for (int k0 = 0; k0 < K; k0 += 16) {
        As[lk + 0][lr] = va.x; As[lk + 1][lr] = va.y; As[lk + 2][lr] = va.z; As[lk + 3][lr] = va.w;
        Bs[lk + 0][lr] = vb.x; Bs[lk + 1][lr] = vb.y; Bs[lk + 2][lr] = vb.z; Bs[lk + 3][lr] = vb.w;
        __syncthreads();
        // prefetch next tile while computing
        if (k0 + 16 < K) {
            va = make_float4(0.f, 0.f, 0.f, 0.f);
            vb = make_float4(0.f, 0.f, 0.f, 0.f);
            if (rowa < M) va = *(const float4*)(A + (size_t)rowa * lda + k0 + 16 + lk);
            if (rowb < N) vb = *(const float4*)(B + (size_t)rowb * ldb + k0 + 16 + lk);
        }
#pragma unroll
        for (int k = 0; k < 16; k++) {
            float4 a4 = *(const float4*)&As[k][ty * 4];
            float4 b4 = *(const float4*)&Bs[k][tx * 4];
            float a[4] = {a4.x, a4.y, a4.z, a4.w};
            float b[4] = {b4.x, b4.y, b4.z, b4.w};
#pragma unroll
            for (int i = 0; i < 4; i++)
#pragma unroll
                for (int j = 0; j < 4; j++) acc[i][j] = fmaf(a[i], b[j], acc[i][j]);
        }
        __syncthreads();
    }
#pragma unroll
    for (int i = 0; i < 4; i++) {
        int r = bm + ty * 4 + i;
        if (r >= M) continue;
#pragma unroll
        for (int j = 0; j < 4; j++) {
            int c = bn + tx * 4 + j;
            if (c < N) C[(size_t)r * ldc + c] = acc[i][j] + (bias ? bias[c] : 0.f);
        }
    }
}

// ---------------- LSTM recurrence: shfl-reduce matvec + self-validating h exchange ------
// grid = 128 CTAs (64 fwd, 64 bwd), 256 threads. CTA owns 8 h-indices (32 gate rows).
// Warp wi owns gate rows [4*wi, 4*wi+4); lane>>3 = row-in-warp, lane&7 = K chunk.
__global__ void __launch_bounds__(256, 1)
lstm_layer(const float* __restrict__ whh_f, const float* __restrict__ whh_b,
           const float* __restrict__ xw_f, const float* __restrict__ xw_b,
           float* __restrict__ hout) {
    __shared__ float sh[512];
    __shared__ float zs[32];

    int dir = blockIdx.x >> 6;
    int j = blockIdx.x & 63;
    int hbase = j * 8;
    const float* W = dir ? whh_b : whh_f;
    const float* xw = dir ? xw_b : xw_f;
    int tid = threadIdx.x;
    int lane = tid & 31;
    int wi = tid >> 5;

    int rloc = wi * 4 + (lane >> 3);      // gate row in CTA (0..31)
    int ck = lane & 7;                    // K chunk
    const int base = ck * 64;
    int growoff = (rloc >> 3) * 512 + hbase + (rloc & 7);   // global gate row

    // weights into registers
    float w[64];
    {
        const float* src = W + (size_t)growoff * 512 + base;
#pragma unroll
        for (int i = 0; i < 64; i += 4) {
            float4 v = *(const float4*)(src + i);
            w[i] = v.x; w[i + 1] = v.y; w[i + 2] = v.z; w[i + 3] = v.w;
        }
    }

    // one-time: poison own hx granules, then grid start-barrier (per direction)
    if (tid == 0) {
        unsigned long long poison =
            ((unsigned long long)__float_as_uint(1e30f) << 32) | __float_as_uint(1e30f);
#pragma unroll
        for (int b = 0; b < 2; b++)
#pragma unroll
            for (int q = 0; q < 4; q++)
                st_rlx64(&g_hx[dir][b][j * 4 + q], poison);
        __threadfence();
        atomicAdd(&g_cnt[dir][0], 1u);
        while (ld_acq(&g_cnt[dir][0]) < (unsigned)RCTAS) { }
    }
    __syncthreads();

    float c_state = 0.f;           // owned by threads 0..7
    int kp = 0, kc = 0;            // t mod 7 (producer), (t-1) mod 7 (consumer)

    for (int t = 0; t < 512; t++) {
        int pos = dir ? (511 - t) : t;
        float coffp = 4.0f * (float)kp;
        float coffc = 4.0f * (float)kc;

        // prefetch xw for this CTA's gate rows (reducing lanes only) — overlaps the poll
        float xg = 0.f;
        if (ck == 0) xg = __ldg(xw + (size_t)pos * GATES + growoff);

        // gather h_prev: every thread polls ONE self-validating 8B granule
        if (t == 0) {
            ((float2*)sh)[tid] = make_float2(0.f, 0.f);
        } else {
            const unsigned long long* src = &g_hx[dir][(t - 1) & 1][tid];
            float lo, hi;
            for (;;) {
                unsigned long long v = ld_rlx64(src);
                lo = __uint_as_float((unsigned)v);
                hi = __uint_as_float((unsigned)(v >> 32));
                if (fabsf(lo - coffc) <= WIN && fabsf(hi - coffc) <= WIN) break;
            }
            ((float2*)sh)[tid] = make_float2(lo - coffc, hi - coffc);
        }
        __syncthreads();   // (1) sh ready

        // matvec partial + warp-local reduction over the 8 chunk lanes
        {
            const float* hv = sh + base;
            float a0 = 0.f, a1 = 0.f, a2 = 0.f, a3 = 0.f;
#pragma unroll
            for (int i = 0; i < 64; i += 4) {
                float4 h4 = *(const float4*)(hv + i);
                a0 = fmaf(w[i + 0], h4.x, a0);
                a1 = fmaf(w[i + 1], h4.y, a1);
                a2 = fmaf(w[i + 2], h4.z, a2);
                a3 = fmaf(w[i + 3], h4.w, a3);
            }
            float s = (a0 + a1) + (a2 + a3);
            s += __shfl_down_sync(0xffffffffu, s, 4, 8);
            s += __shfl_down_sync(0xffffffffu, s, 2, 8);
            s += __shfl_down_sync(0xffffffffu, s, 1, 8);
            if (ck == 0) zs[rloc] = s + xg;
        }
        __syncthreads();   // (2) zs ready

        // warp 0: activations for all 32 gate rows, distribute via shfl, owners update
        if (tid < 32) {
            float z = zs[tid];
            float act = ((tid >> 3) == 2) ? tanhap(z) : sigap(z);
            int k = tid & 7;
            float gi = __shfl_sync(0xffffffffu, act, k);
            float gf = __shfl_sync(0xffffffffu, act, 8 + k);
            float gg = __shfl_sync(0xffffffffu, act, 16 + k);
            float go_ = __shfl_sync(0xffffffffu, act, 24 + k);
            if (tid < 8) {
                c_state = gf * c_state + gi * gg;
                float h = go_ * tanhap(c_state);
                // publish FIRST: v = h + 4*(t%7), packed 2-per-b64
                float vv = h + coffp;
                float partner = __shfl_xor_sync(0x000000FFu, vv, 1);
                if ((tid & 1) == 0) {
                    unsigned long long pk =
                        ((unsigned long long)__float_as_uint(partner) << 32) | __float_as_uint(vv);
                    st_rlx64(&g_hx[dir][t & 1][j * 4 + (tid >> 1)], pk);
                }
                __stcg(hout + (size_t)pos * 1024 + (dir << 9) + hbase + tid, h);
            }
        }
        kc = kp;
        kp = (kp == 6) ? 0 : kp + 1;
    }

    // exit/reset: make counters zero for the next launch / graph replay
    __syncthreads();
    if (tid == 0) {
        __threadfence();
        atomicAdd(&g_exit[dir][0], 1u);
        if (j == 0) {
            while (ld_acq(&g_exit[dir][0]) < (unsigned)RCTAS) { }
            g_cnt[dir][0] = 0u;
            __threadfence();
            atomicExch(&g_exit[dir][0], 0u);
        }
    }
}

// ---------------- pairwise MLP edge scores ----------------
__global__ void pair_score(const float* __restrict__ b1, const float* __restrict__ W2,
                           const float* __restrict__ b2) {
    __shared__ float Sh[32][101];
    __shared__ float Sm[32][101];
    __shared__ float sb1[MLPH], sw2[MLPH];
    int bh = blockIdx.y * 32, bm = blockIdx.x * 32;
    int tid = threadIdx.x;
    for (int i = tid; i < 32 * MLPH; i += 256) {
        int r = i / MLPH, c = i % MLPH;
        Sh[r][c] = g_sh[(size_t)(bh + r) * MLPH + c];
        Sm[r][c] = g_sm[(size_t)(bm + r) * MLPH + c];
    }
    if (tid < MLPH) { sb1[tid] = b1[tid]; sw2[tid] = W2[tid]; }
    __syncthreads();

    int tx = tid & 15, ty = tid >> 4;
    int h0 = ty * 2, m0 = tx * 2;
    float acc00 = 0.f, acc01 = 0.f, acc10 = 0.f, acc11 = 0.f;
    for (int jx = 0; jx < MLPH; jx++) {
        float w = sw2[jx], bb = sb1[jx];
        float a0 = Sh[h0][jx] + bb;
        float a1 = Sh[h0 + 1][jx] + bb;
        float c0 = Sm[m0][jx];
        float c1 = Sm[m0 + 1][jx];
        acc00 = fmaf(tanhap(a0 + c0), w, acc00);
        acc01 = fmaf(tanhap(a0 + c1), w, acc01);
        acc10 = fmaf(tanhap(a1 + c0), w, acc10);
        acc11 = fmaf(tanhap(a1 + c1), w, acc11);
    }
    float b2v = __ldg(b2);
    g_scores[(size_t)(bh + h0) * SEQ + bm + m0]         = acc00 + b2v;
    g_scores[(size_t)(bh + h0) * SEQ + bm + m0 + 1]     = acc01 + b2v;
    g_scores[(size_t)(bh + h0 + 1) * SEQ + bm + m0]     = acc10 + b2v;
    g_scores[(size_t)(bh + h0 + 1) * SEQ + bm + m0 + 1] = acc11 + b2v;
}

// ---------------- softmax over axis 0 ----------------
__global__ void softmax0(float* __restrict__ out) {
    int m = blockIdx.x;
    int tid = threadIdx.x;  // 128
    float v[4];
#pragma unroll
    for (int i = 0; i < 4; i++) v[i] = g_scores[(size_t)(tid + 128 * i) * SEQ + m];
    float mx = fmaxf(fmaxf(v[0], v[1]), fmaxf(v[2], v[3]));
    __shared__ float red[128];
    red[tid] = mx; __syncthreads();
    for (int o = 64; o > 0; o >>= 1) {
        if (tid < o) red[tid] = fmaxf(red[tid], red[tid + o]);
        __syncthreads();
    }
    mx = red[0]; __syncthreads();
    float e[4]; float ssum = 0.f;
#pragma unroll
    for (int i = 0; i < 4; i++) { e[i] = __expf(v[i] - mx); ssum += e[i]; }
    red[tid] = ssum; __syncthreads();
    for (int o = 64; o > 0; o >>= 1) {
        if (tid < o) red[tid] += red[tid + o];
        __syncthreads();
    }
    float inv = 1.f / red[0];
#pragma unroll
    for (int i = 0; i < 4; i++) out[(size_t)(tid + 128 * i) * SEQ + m] = e[i] * inv;
}

// ---------------- launch ----------------
extern "C" void kernel_launch(void* const* d_in, const int* in_sizes, int n_in,
                              void* d_out, int out_size) {
    const int*   wi  = (const int*)d_in[0];
    const int*   pi  = (const int*)d_in[1];
    const float* we  = (const float*)d_in[2];
    const float* pe  = (const float*)d_in[3];
    const float* wih0f = (const float*)d_in[4];
    const float* whh0f = (const float*)d_in[5];
    const float* b0f   = (const float*)d_in[6];
    const float* wih0b = (const float*)d_in[7];
    const float* whh0b = (const float*)d_in[8];
    const float* b0b   = (const float*)d_in[9];
    const float* wih1f = (const float*)d_in[10];
    const float* whh1f = (const float*)d_in[11];
    const float* b1f   = (const float*)d_in[12];
    const float* wih1b = (const float*)d_in[13];
    const float* whh1b = (const float*)d_in[14];
    const float* b1b   = (const float*)d_in[15];
    const float* W1    = (const float*)d_in[16];
    const float* b1    = (const float*)d_in[17];
    const float* W2    = (const float*)d_in[18];
    const float* b2    = (const float*)d_in[19];
    float* out = (float*)d_out;

    float *p_x0, *p_xw0, *p_xw1, *p_h0, *p_h1, *p_sh, *p_sm;
    cudaGetSymbolAddress((void**)&p_x0, g_x0);
    cudaGetSymbolAddress((void**)&p_xw0, g_xw0);
    cudaGetSymbolAddress((void**)&p_xw1, g_xw1);
    cudaGetSymbolAddress((void**)&p_h0, g_h0);
    cudaGetSymbolAddress((void**)&p_h1, g_h1);
    cudaGetSymbolAddress((void**)&p_sh, g_sh);
    cudaGetSymbolAddress((void**)&p_sm, g_sm);

    // 1. embeddings
    embed_kernel<<<SEQ, 256>>>(wi, pi, we, pe);

    // 2. layer0 input GEMMs (both directions in one launch)
    {
        dim3 grid(GATES / 64, SEQ / 64, 2);
        gemm_dual<<<grid, 256>>>(p_x0, IN0, wih0f, wih0b, IN0, b0f, b0b,
                                 p_xw0, p_xw1, GATES, SEQ, GATES, IN0);
    }

    // 3. layer0 recurrence
    lstm_layer<<<2 * RCTAS, 256>>>(whh0f, whh0b, p_xw0, p_xw1, p_h0);

    // 4. layer1 input GEMMs (both directions in one launch)
    {
        dim3 grid(GATES / 64, SEQ / 64, 2);
        gemm_dual<<<grid, 256>>>(p_h0, IN1, wih1f, wih1b, IN1, b1f, b1b,
                                 p_xw0, p_xw1, GATES, SEQ, GATES, IN1);
    }

    // 5. layer1 recurrence
    lstm_layer<<<2 * RCTAS, 256>>>(whh1f, whh1b, p_xw0, p_xw1, p_h1);

    // 6. MLP projections, both halves in one launch (W1 is [100, 2048] -> ldb = PAIRD)
    {
        dim3 grid((MLPH + 63) / 64, SEQ / 64, 2);
        gemm_dual<<<grid, 256>>>(p_h1, 2 * HID, W1, W1 + 1024, PAIRD, nullptr, nullptr,
                                 p_sh, p_sm, MLPH, SEQ, MLPH, 2 * HID);
    }

    // 7. pairwise scores
    {
        dim3 grid(SEQ / 32, SEQ / 32);
        pair_score<<<grid, 256>>>(b1, W2, b2);
    }

    // 8. softmax over heads (axis 0)
    softmax0<<<SEQ, 128>>>(out);
}

// round 9
// speedup vs baseline: 2.4348x; 2.4348x over previous
#include <cuda_runtime.h>
#include <math.h>
#include <stdint.h>

#define SEQ   512
#define HID   512
#define IN0   1088
#define IN1   1024
#define GATES 2048
#define MLPH  100
#define PAIRD 2048
#define RCTAS 64   // CTAs per LSTM direction
#define WIN   1.5f

// ---------------- device scratch (no allocations allowed) ----------------
__device__ float g_x0[SEQ * IN0];
__device__ float g_xw0[SEQ * GATES];
__device__ float g_xw1[SEQ * GATES];
__device__ float g_h0[SEQ * 2 * HID];
__device__ float g_h1[SEQ * 2 * HID];
__device__ float g_sh[SEQ * MLPH];
__device__ float g_sm[SEQ * MLPH];
__device__ float g_scores[SEQ * SEQ];
// self-validating h exchange: [dir][buffer=t&1][granule 0..255] (8B = 2 h values)
__device__ __align__(128) unsigned long long g_hx[2][2][256];
__device__ __align__(128) unsigned g_cnt[2][32];    // one-time start barrier
__device__ __align__(128) unsigned g_exit[2][32];   // exit/reset barrier

// ---------------- helpers ----------------
__device__ __forceinline__ unsigned ld_acq(const unsigned* p) {
    unsigned v;
    asm volatile("ld.acquire.gpu.u32 %0, [%1];" : "=r"(v) : "l"(p) : "memory");
    return v;
}
__device__ __forceinline__ unsigned long long ld_rlx64(const unsigned long long* p) {
    unsigned long long v;
    asm volatile("ld.relaxed.gpu.global.b64 %0, [%1];" : "=l"(v) : "l"(p) : "memory");
    return v;
}
__device__ __forceinline__ void st_rlx64(unsigned long long* p, unsigned long long v) {
    asm volatile("st.relaxed.gpu.global.b64 [%0], %1;" :: "l"(p), "l"(v) : "memory");
}
__device__ __forceinline__ float tanhap(float x) {             // HW tanh
    float y;
    asm("tanh.approx.f32 %0, %1;" : "=f"(y) : "f"(x));
    return y;
}
__device__ __forceinline__ float sigap(float x) {              // sigmoid via HW tanh
    return fmaf(0.5f, tanhap(0.5f * x), 0.5f);
}

// ---------------- embeddings ----------------
__global__ void embed_kernel(const int* __restrict__ wi, const int* __restrict__ pi,
                             const float* __restrict__ we, const float* __restrict__ pe) {
    int t = blockIdx.x;
    int w = wi[t], p = pi[t];
    const float* wr = we + (size_t)w * 1024;
    const float* pr = pe + (size_t)p * 64;
    float* out = g_x0 + (size_t)t * IN0;
    for (int i = threadIdx.x; i < 1024; i += blockDim.x) out[i] = wr[i];
    for (int i = threadIdx.x; i < 64; i += blockDim.x) out[1024 + i] = pr[i];
}

// ---- dual GEMM: z selects (B, bias, C); C[M,N] = A[M,K] * B[N,K]^T (+bias) ----
// BM=64, BN=64, BK=16, 256 threads, 4x4 register tile, register double-buffered.
__global__ void gemm_dual(const float* __restrict__ A, int lda,
                          const float* __restrict__ B0, const float* __restrict__ B1, int ldb,
                          const float* __restrict__ bias0, const float* __restrict__ bias1,
                          float* __restrict__ C0, float* __restrict__ C1, int ldc,
                          int M, int N, int K) {
    const float* B = blockIdx.z ? B1 : B0;
    const float* bias = blockIdx.z ? bias1 : bias0;
    float* C = blockIdx.z ? C1 : C0;

    __shared__ __align__(16) float As[16][68];
    __shared__ __align__(16) float Bs[16][68];
    int bm = blockIdx.y * 64, bn = blockIdx.x * 64;
    int tid = threadIdx.x;
    int tx = tid & 15, ty = tid >> 4;
    int lr = tid >> 2;
    int lk = (tid & 3) * 4;

    float acc[4][4];
#pragma unroll
    for (int i = 0; i < 4; i++)
#pragma unroll
        for (int j = 0; j < 4; j++) acc[i][j] = 0.f;

    int rowa = bm + lr;
    int rowb = bn + lr;

    // preload tile 0
    float4 va = make_float4(0.f, 0.f, 0.f, 0.f);
    float4 vb = make_float4(0.f, 0.f, 0.f, 0.f);
    if (rowa < M) va = *(const float4*)(A + (size_t)rowa * lda + lk);
    if (rowb < N) vb = *(const float4*)(B + (size_t)rowb * ldb + lk);

    for (int k0 = 0; k0 < K; k0 += 16) {
        As[lk + 0][lr] = va.x; As[lk + 1][lr] = va.y; As[lk + 2][lr] = va.z; As[lk + 3][lr] = va.w;
        Bs[lk + 0][lr] = vb.x; Bs[lk + 1][lr] = vb.y; Bs[lk + 2][lr] = vb.z; Bs[lk + 3][lr] = vb.w;
        __syncthreads();
        // prefetch next tile while computing
        if (k0 + 16 < K) {
            va = make_float4(0.f, 0.f, 0.f, 0.f);
            vb = make_float4(0.f, 0.f, 0.f, 0.f);
            if (rowa < M) va = *(const float4*)(A + (size_t)rowa * lda + k0 + 16 + lk);
            if (rowb < N) vb = *(const float4*)(B + (size_t)rowb * ldb + k0 + 16 + lk);
        }
#pragma unroll
        for (int k = 0; k < 16; k++) {
            float4 a4 = *(const float4*)&As[k][ty * 4];
            float4 b4 = *(const float4*)&Bs[k][tx * 4];
            float a[4] = {a4.x, a4.y, a4.z, a4.w};
            float b[4] = {b4.x, b4.y, b4.z, b4.w};
#pragma unroll
            for (int i = 0; i < 4; i++)
#pragma unroll
                for (int j = 0; j < 4; j++) acc[i][j] = fmaf(a[i], b[j], acc[i][j]);
        }
        __syncthreads();
    }
#pragma unroll
    for (int i = 0; i < 4; i++) {
        int r = bm + ty * 4 + i;
        if (r >= M) continue;
#pragma unroll
        for (int j = 0; j < 4; j++) {
            int c = bn + tx * 4 + j;
            if (c < N) C[(size_t)r * ldc + c] = acc[i][j] + (bias ? bias[c] : 0.f);
        }
    }
}

// ---------------- LSTM recurrence: register weights + self-validating h exchange --------
// (R7-winning structure, restored verbatim)
// grid = 128 CTAs (64 fwd, 64 bwd), 256 threads. CTA owns 8 h-indices (32 gate rows).
// h published as v = h + 4*(t mod 7), double-buffered by t&1; value IS the sync.
__global__ void __launch_bounds__(256, 1)
lstm_layer(const float* __restrict__ whh_f, const float* __restrict__ whh_b,
           const float* __restrict__ xw_f, const float* __restrict__ xw_b,
           float* __restrict__ hout) {
    __shared__ float sh[512];
    __shared__ float zp[32 * 9];
    __shared__ float sact[32];

    int dir = blockIdx.x >> 6;
    int j = blockIdx.x & 63;
    int hbase = j * 8;
    const float* W = dir ? whh_b : whh_f;
    const float* xw = dir ? xw_b : xw_f;
    int tid = threadIdx.x;

    int row = tid & 31;            // gate row within CTA (0..31)
    int ck = tid >> 5;             // K chunk (0..7)
    const int base = ck * 64;

    // weights into registers
    float w[64];
    {
        const float* src = W + (size_t)((row >> 3) * 512 + hbase + (row & 7)) * 512 + base;
#pragma unroll
        for (int i = 0; i < 64; i += 4) {
            float4 v = *(const float4*)(src + i);
            w[i] = v.x; w[i + 1] = v.y; w[i + 2] = v.z; w[i + 3] = v.w;
        }
    }

    // one-time: poison own hx granules, then grid start-barrier (per direction)
    if (tid == 0) {
        unsigned long long poison =
            ((unsigned long long)__float_as_uint(1e30f) << 32) | __float_as_uint(1e30f);
#pragma unroll
        for (int b = 0; b < 2; b++)
#pragma unroll
            for (int q = 0; q < 4; q++)
                st_rlx64(&g_hx[dir][b][j * 4 + q], poison);
        __threadfence();
        atomicAdd(&g_cnt[dir][0], 1u);
        while (ld_acq(&g_cnt[dir][0]) < (unsigned)RCTAS) { }
    }
    __syncthreads();

    float c_state = 0.f;           // owned by threads 0..7
    int kp = 0, kc = 0;            // t mod 7 (producer), (t-1) mod 7 (consumer)

    for (int t = 0; t < 512; t++) {
        int pos = dir ? (511 - t) : t;
        float coffp = 4.0f * (float)kp;
        float coffc = 4.0f * (float)kc;

        // prefetch gate inputs (independent of h) — overlaps the poll below
        float xg = 0.f;
        if (tid < 32) {
            const float* xr = xw + (size_t)pos * GATES + (tid >> 3) * 512 + hbase + (tid & 7);
            xg = __ldg(xr);
        }

        // gather h_prev: every thread polls ONE self-validating 8B granule
        if (t == 0) {
            ((float2*)sh)[tid] = make_float2(0.f, 0.f);
        } else {
            const unsigned long long* src = &g_hx[dir][(t - 1) & 1][tid];
            float lo, hi;
            for (;;) {
                unsigned long long v = ld_rlx64(src);
                lo = __uint_as_float((unsigned)v);
                hi = __uint_as_float((unsigned)(v >> 32));
                if (fabsf(lo - coffc) <= WIN && fabsf(hi - coffc) <= WIN) break;
            }
            ((float2*)sh)[tid] = make_float2(lo - coffc, hi - coffc);
        }
        __syncthreads();   // sh ready

        // matvec partial: register weights x broadcast smem h
        {
            const float* hv = sh + base;
            float a0 = 0.f, a1 = 0.f, a2 = 0.f, a3 = 0.f;
#pragma unroll
            for (int i = 0; i < 64; i += 4) {
                float4 h4 = *(const float4*)(hv + i);
                a0 = fmaf(w[i + 0], h4.x, a0);
                a1 = fmaf(w[i + 1], h4.y, a1);
                a2 = fmaf(w[i + 2], h4.z, a2);
                a3 = fmaf(w[i + 3], h4.w, a3);
            }
            zp[row * 9 + ck] = (a0 + a1) + (a2 + a3);
        }
        __syncthreads();   // zp ready

        // warp 0: gate-row sums + activations; 8 owners update state + publish
        if (tid < 32) {
            const float* zr = zp + tid * 9;
            float z = xg;
#pragma unroll
            for (int c = 0; c < 8; c++) z += zr[c];
            sact[tid] = ((tid >> 3) == 2) ? tanhap(z) : sigap(z);
        }
        __syncwarp();
        if (tid < 8) {
            float gi = sact[tid];
            float gf = sact[8 + tid];
            float gg = sact[16 + tid];
            float go_ = sact[24 + tid];
            c_state = gf * c_state + gi * gg;
            float h = go_ * tanhap(c_state);
            __stcg(hout + (size_t)pos * 1024 + (dir << 9) + hbase + tid, h);
            // publish: v = h + 4*(t%7), packed 2-per-b64, fire-and-forget
            float vv = h + coffp;
            float partner = __shfl_xor_sync(0x000000FFu, vv, 1);
            if ((tid & 1) == 0) {
                unsigned long long pk =
                    ((unsigned long long)__float_as_uint(partner) << 32) | __float_as_uint(vv);
                st_rlx64(&g_hx[dir][t & 1][j * 4 + (tid >> 1)], pk);
            }
        }
        kc = kp;
        kp = (kp == 6) ? 0 : kp + 1;
    }

    // exit/reset: make counters zero for the next launch / graph replay
    __syncthreads();
    if (tid == 0) {
        __threadfence();
        atomicAdd(&g_exit[dir][0], 1u);
        if (j == 0) {
            while (ld_acq(&g_exit[dir][0]) < (unsigned)RCTAS) { }
            g_cnt[dir][0] = 0u;
            __threadfence();
            atomicExch(&g_exit[dir][0], 0u);
        }
    }
}

// ---------------- pairwise MLP edge scores ----------------
__global__ void pair_score(const float* __restrict__ b1, const float* __restrict__ W2,
                           const float* __restrict__ b2) {
    __shared__ float Sh[32][101];
    __shared__ float Sm[32][101];
    __shared__ float sb1[MLPH], sw2[MLPH];
    int bh = blockIdx.y * 32, bm = blockIdx.x * 32;
    int tid = threadIdx.x;
    for (int i = tid; i < 32 * MLPH; i += 256) {
        int r = i / MLPH, c = i % MLPH;
        Sh[r][c] = g_sh[(size_t)(bh + r) * MLPH + c];
        Sm[r][c] = g_sm[(size_t)(bm + r) * MLPH + c];
    }
    if (tid < MLPH) { sb1[tid] = b1[tid]; sw2[tid] = W2[tid]; }
    __syncthreads();

    int tx = tid & 15, ty = tid >> 4;
    int h0 = ty * 2, m0 = tx * 2;
    float acc00 = 0.f, acc01 = 0.f, acc10 = 0.f, acc11 = 0.f;
    for (int jx = 0; jx < MLPH; jx++) {
        float w = sw2[jx], bb = sb1[jx];
        float a0 = Sh[h0][jx] + bb;
        float a1 = Sh[h0 + 1][jx] + bb;
        float c0 = Sm[m0][jx];
        float c1 = Sm[m0 + 1][jx];
        acc00 = fmaf(tanhap(a0 + c0), w, acc00);
        acc01 = fmaf(tanhap(a0 + c1), w, acc01);
        acc10 = fmaf(tanhap(a1 + c0), w, acc10);
        acc11 = fmaf(tanhap(a1 + c1), w, acc11);
    }
    float b2v = __ldg(b2);
    g_scores[(size_t)(bh + h0) * SEQ + bm + m0]         = acc00 + b2v;
    g_scores[(size_t)(bh + h0) * SEQ + bm + m0 + 1]     = acc01 + b2v;
    g_scores[(size_t)(bh + h0 + 1) * SEQ + bm + m0]     = acc10 + b2v;
    g_scores[(size_t)(bh + h0 + 1) * SEQ + bm + m0 + 1] = acc11 + b2v;
}

// ---------------- softmax over axis 0 ----------------
__global__ void softmax0(float* __restrict__ out) {
    int m = blockIdx.x;
    int tid = threadIdx.x;  // 128
    float v[4];
#pragma unroll
    for (int i = 0; i < 4; i++) v[i] = g_scores[(size_t)(tid + 128 * i) * SEQ + m];
    float mx = fmaxf(fmaxf(v[0], v[1]), fmaxf(v[2], v[3]));
    __shared__ float red[128];
    red[tid] = mx; __syncthreads();
    for (int o = 64; o > 0; o >>= 1) {
        if (tid < o) red[tid] = fmaxf(red[tid], red[tid + o]);
        __syncthreads();
    }
    mx = red[0]; __syncthreads();
    float e[4]; float ssum = 0.f;
#pragma unroll
    for (int i = 0; i < 4; i++) { e[i] = __expf(v[i] - mx); ssum += e[i]; }
    red[tid] = ssum; __syncthreads();
    for (int o = 64; o > 0; o >>= 1) {
        if (tid < o) red[tid] += red[tid + o];
        __syncthreads();
    }
    float inv = 1.f / red[0];
#pragma unroll
    for (int i = 0; i < 4; i++) out[(size_t)(tid + 128 * i) * SEQ + m] = e[i] * inv;
}

// ---------------- launch ----------------
extern "C" void kernel_launch(void* const* d_in, const int* in_sizes, int n_in,
                              void* d_out, int out_size) {
    const int*   wi  = (const int*)d_in[0];
    const int*   pi  = (const int*)d_in[1];
    const float* we  = (const float*)d_in[2];
    const float* pe  = (const float*)d_in[3];
    const float* wih0f = (const float*)d_in[4];
    const float* whh0f = (const float*)d_in[5];
    const float* b0f   = (const float*)d_in[6];
    const float* wih0b = (const float*)d_in[7];
    const float* whh0b = (const float*)d_in[8];
    const float* b0b   = (const float*)d_in[9];
    const float* wih1f = (const float*)d_in[10];
    const float* whh1f = (const float*)d_in[11];
    const float* b1f   = (const float*)d_in[12];
    const float* wih1b = (const float*)d_in[13];
    const float* whh1b = (const float*)d_in[14];
    const float* b1b   = (const float*)d_in[15];
    const float* W1    = (const float*)d_in[16];
    const float* b1    = (const float*)d_in[17];
    const float* W2    = (const float*)d_in[18];
    const float* b2    = (const float*)d_in[19];
    float* out = (float*)d_out;

    float *p_x0, *p_xw0, *p_xw1, *p_h0, *p_h1, *p_sh, *p_sm;
    cudaGetSymbolAddress((void**)&p_x0, g_x0);
    cudaGetSymbolAddress((void**)&p_xw0, g_xw0);
    cudaGetSymbolAddress((void**)&p_xw1, g_xw1);
    cudaGetSymbolAddress((void**)&p_h0, g_h0);
    cudaGetSymbolAddress((void**)&p_h1, g_h1);
    cudaGetSymbolAddress((void**)&p_sh, g_sh);
    cudaGetSymbolAddress((void**)&p_sm, g_sm);

    // 1. embeddings
    embed_kernel<<<SEQ, 256>>>(wi, pi, we, pe);

    // 2. layer0 input GEMMs (both directions in one launch)
    {
        dim3 grid(GATES / 64, SEQ / 64, 2);
        gemm_dual<<<grid, 256>>>(p_x0, IN0, wih0f, wih0b, IN0, b0f, b0b,
                                 p_xw0, p_xw1, GATES, SEQ, GATES, IN0);
    }

    // 3. layer0 recurrence
    lstm_layer<<<2 * RCTAS, 256>>>(whh0f, whh0b, p_xw0, p_xw1, p_h0);

    // 4. layer1 input GEMMs (both directions in one launch)
    {
        dim3 grid(GATES / 64, SEQ / 64, 2);
        gemm_dual<<<grid, 256>>>(p_h0, IN1, wih1f, wih1b, IN1, b1f, b1b,
                                 p_xw0, p_xw1, GATES, SEQ, GATES, IN1);
    }

    // 5. layer1 recurrence
    lstm_layer<<<2 * RCTAS, 256>>>(whh1f, whh1b, p_xw0, p_xw1, p_h1);

    // 6. MLP projections, both halves in one launch (W1 is [100, 2048] -> ldb = PAIRD)
    {
        dim3 grid((MLPH + 63) / 64, SEQ / 64, 2);
        gemm_dual<<<grid, 256>>>(p_h1, 2 * HID, W1, W1 + 1024, PAIRD, nullptr, nullptr,
                                 p_sh, p_sm, MLPH, SEQ, MLPH, 2 * HID);
    }

    // 7. pairwise scores
    {
        dim3 grid(SEQ / 32, SEQ / 32);
        pair_score<<<grid, 256>>>(b1, W2, b2);
    }

    // 8. softmax over heads (axis 0)
    softmax0<<<SEQ, 128>>>(out);
}